// round 3
// baseline (speedup 1.0000x reference)
#include <cuda_runtime.h>
#include <math.h>
#include <float.h>

// ---------------- scratch (device globals; no allocs allowed) ----------------
__device__ float g_a1[33554432];  // [8,64,256,256] enc1 out / dec convT2 out
__device__ float g_a2[8388608];   // [8,64,128,128] enc2 out / dec convT1 out
__device__ float g_a3[2097152];   // [8,64,64,64]   enc3 out
__device__ float g_z [2097152];   // [8,64,64,64]   encoder z
__device__ float g_zq[2097152];   // [8,64,64,64]   quantized z
__device__ float g_d1[2097152];   // [8,64,64,64]   dec conv1 out
__device__ float g_dmin[32768];   // per-position min distance
__device__ float g_e2[512];       // codebook row norms

__device__ __forceinline__ float* g_buf(int s) {
    switch (s) {
        case 1: return g_a1;
        case 2: return g_a2;
        case 3: return g_a3;
        case 4: return g_z;
        case 5: return g_zq;
        case 6: return g_d1;
    }
    return nullptr;
}

// ---------------- conv1: cin=1, k4 s2 p1, 1->64, relu, 512->256 ----------------
__global__ void k_conv1(const float* __restrict__ x, const float* __restrict__ w,
                        const float* __restrict__ bias)
{
    __shared__ float sw[1024];
    __shared__ float sb[64];
    const int tid = threadIdx.x;
    for (int i = tid; i < 1024; i += 256) sw[i] = w[i];
    if (tid < 64) sb[tid] = bias[tid];
    __syncthreads();

    const int gid = blockIdx.x * 256 + tid;      // 8*256*256 total
    const int ox = gid & 255;
    const int oy = (gid >> 8) & 255;
    const int b  = gid >> 16;
    const int iy0 = oy * 2 - 1, ix0 = ox * 2 - 1;
    const float* xb = x + (size_t)b * 512 * 512;

    float v[16];
#pragma unroll
    for (int ky = 0; ky < 4; ky++) {
#pragma unroll
        for (int kx = 0; kx < 4; kx++) {
            int iy = iy0 + ky, ix = ix0 + kx;
            float t = 0.f;
            if ((unsigned)iy < 512u && (unsigned)ix < 512u) t = xb[iy * 512 + ix];
            v[ky * 4 + kx] = t;
        }
    }
    float* ob = g_a1 + (size_t)b * 64 * 65536 + oy * 256 + ox;
#pragma unroll 4
    for (int co = 0; co < 64; co++) {
        float a = sb[co];
#pragma unroll
        for (int t = 0; t < 16; t++) a += v[t] * sw[co * 16 + t];
        ob[(size_t)co * 65536] = fmaxf(a, 0.f);
    }
}

// ---------------- generic k4 s2 p1, 64->64, relu; 32x32 output tile ----------------
__global__ void k_conv4x4s2(int in_sel, const float* __restrict__ w,
                            const float* __restrict__ bias, int out_sel,
                            int Hin, int Win)
{
    __shared__ float s_in[66 * 67];
    __shared__ float s_w[128];
    const float* in = g_buf(in_sel);
    float* out = g_buf(out_sel);

    const int tid = threadIdx.x;
    const int tx = tid & 15, ty = tid >> 4;
    const int b   = blockIdx.z >> 3;
    const int co0 = (blockIdx.z & 7) << 3;
    const int oy0 = blockIdx.y << 5, ox0 = blockIdx.x << 5;
    const int iy0 = (oy0 << 1) - 1, ix0 = (ox0 << 1) - 1;
    const int Hout = Hin >> 1, Wout = Win >> 1;
    const float* inb = in + (size_t)b * 64 * Hin * Win;

    float acc[4][8];
#pragma unroll
    for (int p = 0; p < 4; p++)
#pragma unroll
        for (int c = 0; c < 8; c++) acc[p][c] = 0.f;

    for (int ci = 0; ci < 64; ci++) {
        __syncthreads();
        const float* ic = inb + (size_t)ci * Hin * Win;
        for (int i = tid; i < 66 * 66; i += 256) {
            int r = i / 66, c = i - r * 66;
            int iy = iy0 + r, ix = ix0 + c;
            float t = 0.f;
            if ((unsigned)iy < (unsigned)Hin && (unsigned)ix < (unsigned)Win)
                t = ic[iy * Win + ix];
            s_in[r * 67 + c] = t;
        }
        if (tid < 128)
            s_w[tid] = w[(((co0 + (tid >> 4)) * 64) + ci) * 16 + (tid & 15)];
        __syncthreads();

#pragma unroll
        for (int ky = 0; ky < 4; ky++) {
#pragma unroll
            for (int kx = 0; kx < 4; kx++) {
                float v00 = s_in[(4 * ty + ky) * 67 + 4 * tx + kx];
                float v01 = s_in[(4 * ty + ky) * 67 + 4 * tx + kx + 2];
                float v10 = s_in[(4 * ty + ky + 2) * 67 + 4 * tx + kx];
                float v11 = s_in[(4 * ty + ky + 2) * 67 + 4 * tx + kx + 2];
#pragma unroll
                for (int co = 0; co < 8; co++) {
                    float wv = s_w[(co << 4) + (ky << 2) + kx];
                    acc[0][co] += v00 * wv;
                    acc[1][co] += v01 * wv;
                    acc[2][co] += v10 * wv;
                    acc[3][co] += v11 * wv;
                }
            }
        }
    }

#pragma unroll
    for (int co = 0; co < 8; co++) {
        float bv = bias[co0 + co];
        float* ob = out + ((size_t)(b * 64 + co0 + co) * Hout + oy0) * Wout + ox0;
#pragma unroll
        for (int dy = 0; dy < 2; dy++)
#pragma unroll
            for (int dx = 0; dx < 2; dx++) {
                float v = acc[dy * 2 + dx][co] + bv;
                ob[(2 * ty + dy) * Wout + 2 * tx + dx] = fmaxf(v, 0.f);
            }
    }
}

// ---------------- k3 s1 p1, 64->64 on 64x64 images; optional relu ----------------
__global__ void k_conv3x3(int in_sel, const float* __restrict__ w,
                          const float* __restrict__ bias, int out_sel, int do_relu)
{
    __shared__ float s_in[34 * 35];
    __shared__ float s_w[72];
    const float* in = g_buf(in_sel);
    float* out = g_buf(out_sel);

    const int tid = threadIdx.x;
    const int tx = tid & 15, ty = tid >> 4;
    const int b   = blockIdx.z >> 3;
    const int co0 = (blockIdx.z & 7) << 3;
    const int oy0 = blockIdx.y << 5, ox0 = blockIdx.x << 5;
    const int iy0 = oy0 - 1, ix0 = ox0 - 1;
    const float* inb = in + (size_t)b * 64 * 4096;

    float acc[4][8];
#pragma unroll
    for (int p = 0; p < 4; p++)
#pragma unroll
        for (int c = 0; c < 8; c++) acc[p][c] = 0.f;

    for (int ci = 0; ci < 64; ci++) {
        __syncthreads();
        const float* ic = inb + ci * 4096;
        for (int i = tid; i < 34 * 34; i += 256) {
            int r = i / 34, c = i - r * 34;
            int iy = iy0 + r, ix = ix0 + c;
            float t = 0.f;
            if ((unsigned)iy < 64u && (unsigned)ix < 64u) t = ic[(iy << 6) + ix];
            s_in[r * 35 + c] = t;
        }
        if (tid < 72)
            s_w[tid] = w[(((co0 + tid / 9) * 64) + ci) * 9 + (tid % 9)];
        __syncthreads();

#pragma unroll
        for (int ky = 0; ky < 3; ky++) {
#pragma unroll
            for (int kx = 0; kx < 3; kx++) {
                float v00 = s_in[(2 * ty + ky) * 35 + 2 * tx + kx];
                float v01 = s_in[(2 * ty + ky) * 35 + 2 * tx + kx + 1];
                float v10 = s_in[(2 * ty + ky + 1) * 35 + 2 * tx + kx];
                float v11 = s_in[(2 * ty + ky + 1) * 35 + 2 * tx + kx + 1];
#pragma unroll
                for (int co = 0; co < 8; co++) {
                    float wv = s_w[co * 9 + ky * 3 + kx];
                    acc[0][co] += v00 * wv;
                    acc[1][co] += v01 * wv;
                    acc[2][co] += v10 * wv;
                    acc[3][co] += v11 * wv;
                }
            }
        }
    }

#pragma unroll
    for (int co = 0; co < 8; co++) {
        float bv = bias[co0 + co];
        float* ob = out + ((size_t)(b * 64 + co0 + co) * 64 + oy0) * 64 + ox0;
#pragma unroll
        for (int dy = 0; dy < 2; dy++)
#pragma unroll
            for (int dx = 0; dx < 2; dx++) {
                float v = acc[dy * 2 + dx][co] + bv;
                if (do_relu) v = fmaxf(v, 0.f);
                ob[(2 * ty + dy) * 64 + 2 * tx + dx] = v;
            }
    }
}

// ---------------- convT k4 s2 p1 (torch layout [Cin,Cout,4,4]), 64->64, relu -----
__global__ void k_convt(int in_sel, const float* __restrict__ w,
                        const float* __restrict__ bias, int out_sel,
                        int Hin, int Win)
{
    __shared__ float s_in[18 * 19];
    __shared__ float s_w[128];
    const float* in = g_buf(in_sel);
    float* out = g_buf(out_sel);

    const int tid = threadIdx.x;
    const int tx = tid & 15, ty = tid >> 4;
    const int b   = blockIdx.z >> 3;
    const int co0 = (blockIdx.z & 7) << 3;
    const int oy0 = blockIdx.y << 5, ox0 = blockIdx.x << 5;
    const int iy0 = (oy0 >> 1) - 1, ix0 = (ox0 >> 1) - 1;
    const int Hout = Hin << 1, Wout = Win << 1;
    const float* inb = in + (size_t)b * 64 * Hin * Win;

    float acc[4][8];
#pragma unroll
    for (int p = 0; p < 4; p++)
#pragma unroll
        for (int c = 0; c < 8; c++) acc[p][c] = 0.f;

    for (int ci = 0; ci < 64; ci++) {
        __syncthreads();
        const float* ic = inb + (size_t)ci * Hin * Win;
        for (int i = tid; i < 18 * 18; i += 256) {
            int r = i / 18, c = i - r * 18;
            int iy = iy0 + r, ix = ix0 + c;
            float t = 0.f;
            if ((unsigned)iy < (unsigned)Hin && (unsigned)ix < (unsigned)Win)
                t = ic[iy * Win + ix];
            s_in[r * 19 + c] = t;
        }
        if (tid < 128)
            s_w[tid] = w[((ci * 64) + co0 + (tid >> 4)) * 16 + (tid & 15)];
        __syncthreads();

        float v[3][3];
#pragma unroll
        for (int r = 0; r < 3; r++)
#pragma unroll
            for (int c = 0; c < 3; c++)
                v[r][c] = s_in[(ty + r) * 19 + tx + c];

        // out(oy,ox): iy=(oy+1-ky)/2 valid when parity matches.
        // dy = 1-(ky&1), local row offset rr = (4-ky)>>1 (same for kx).
#pragma unroll
        for (int ky = 0; ky < 4; ky++) {
            const int dy = 1 - (ky & 1);
            const int rr = (4 - ky) >> 1;
#pragma unroll
            for (int kx = 0; kx < 4; kx++) {
                const int dx = 1 - (kx & 1);
                const int cc = (4 - kx) >> 1;
                float vv = v[rr][cc];
#pragma unroll
                for (int co = 0; co < 8; co++)
                    acc[dy * 2 + dx][co] += vv * s_w[(co << 4) + (ky << 2) + kx];
            }
        }
    }

#pragma unroll
    for (int co = 0; co < 8; co++) {
        float bv = bias[co0 + co];
        float* ob = out + ((size_t)(b * 64 + co0 + co) * Hout + oy0) * Wout + ox0;
#pragma unroll
        for (int dy = 0; dy < 2; dy++)
#pragma unroll
            for (int dx = 0; dx < 2; dx++) {
                float v2 = acc[dy * 2 + dx][co] + bv;
                ob[(2 * ty + dy) * Wout + 2 * tx + dx] = fmaxf(v2, 0.f);
            }
    }
}

// ---------------- convT3: 64->1, sigmoid, 256->512, writes d_out ----------------
__global__ void k_convt_out(const float* __restrict__ w,
                            const float* __restrict__ bias, float* __restrict__ out)
{
    __shared__ float s_in[18 * 19];
    __shared__ float s_w[16];
    const int tid = threadIdx.x;
    const int tx = tid & 15, ty = tid >> 4;
    const int b = blockIdx.z;
    const int oy0 = blockIdx.y << 5, ox0 = blockIdx.x << 5;
    const int iy0 = (oy0 >> 1) - 1, ix0 = (ox0 >> 1) - 1;
    const float* inb = g_a1 + (size_t)b * 64 * 65536;   // Hin=Win=256

    float acc[4] = {0.f, 0.f, 0.f, 0.f};

    for (int ci = 0; ci < 64; ci++) {
        __syncthreads();
        const float* ic = inb + (size_t)ci * 65536;
        for (int i = tid; i < 18 * 18; i += 256) {
            int r = i / 18, c = i - r * 18;
            int iy = iy0 + r, ix = ix0 + c;
            float t = 0.f;
            if ((unsigned)iy < 256u && (unsigned)ix < 256u) t = ic[(iy << 8) + ix];
            s_in[r * 19 + c] = t;
        }
        if (tid < 16) s_w[tid] = w[ci * 16 + tid];   // [Cin,1,4,4]
        __syncthreads();

        float v[3][3];
#pragma unroll
        for (int r = 0; r < 3; r++)
#pragma unroll
            for (int c = 0; c < 3; c++)
                v[r][c] = s_in[(ty + r) * 19 + tx + c];

#pragma unroll
        for (int ky = 0; ky < 4; ky++) {
            const int dy = 1 - (ky & 1);
            const int rr = (4 - ky) >> 1;
#pragma unroll
            for (int kx = 0; kx < 4; kx++) {
                const int dx = 1 - (kx & 1);
                const int cc = (4 - kx) >> 1;
                acc[dy * 2 + dx] += v[rr][cc] * s_w[(ky << 2) + kx];
            }
        }
    }

    float bv = bias[0];
#pragma unroll
    for (int dy = 0; dy < 2; dy++)
#pragma unroll
        for (int dx = 0; dx < 2; dx++) {
            float s = acc[dy * 2 + dx] + bv;
            s = 1.f / (1.f + expf(-s));
            out[((size_t)b * 512 + oy0 + 2 * ty + dy) * 512 + ox0 + 2 * tx + dx] = s;
        }
}

// ---------------- VQ ----------------
__global__ void k_e2(const float* __restrict__ cb)
{
    int k = threadIdx.x;   // 512 threads
    float s = 0.f;
    for (int c = 0; c < 64; c++) {
        float v = cb[k * 64 + c];
        s += v * v;
    }
    g_e2[k] = s;
}

// 32 positions per block, 256 threads. Codebook staged in 64-code chunks.
__global__ void k_vq(const float* __restrict__ cb)
{
    __shared__ float s_z[32 * 65];
    __shared__ float s_cb[64 * 65];
    __shared__ float s_z2[32];
    __shared__ float s_bd[32];
    __shared__ int   s_bk[32];

    const int tid = threadIdx.x;
    const int pos0 = blockIdx.x * 32;
    const int b = pos0 >> 12;          // 4096 positions per batch image
    const int hw0 = pos0 & 4095;
    const float* zb = g_z + (size_t)b * 262144;

    // load 32 z vectors: thread t -> pos t&31, channels (t>>5)*8..+8
    {
        int pl = tid & 31, cb8 = tid >> 5;
        for (int cc = 0; cc < 8; cc++) {
            int c = cb8 * 8 + cc;
            s_z[pl * 65 + c] = zb[(size_t)c * 4096 + hw0 + pl];
        }
    }
    __syncthreads();
    if (tid < 32) {
        float s = 0.f;
        for (int c = 0; c < 64; c++) { float t = s_z[tid * 65 + c]; s += t * t; }
        s_z2[tid] = s;
    }

    const int j = tid & 7;    // code sub-lane
    const int p = tid >> 3;   // position 0..31
    float best_d = FLT_MAX;
    int best_k = 0;

    for (int chunk = 0; chunk < 8; chunk++) {
        __syncthreads();
        for (int i = tid; i < 4096; i += 256) {
            int code = i >> 6, c = i & 63;
            s_cb[code * 65 + c] = cb[chunk * 4096 + i];
        }
        __syncthreads();

        float dot[8];
#pragma unroll
        for (int jj = 0; jj < 8; jj++) dot[jj] = 0.f;
        for (int c = 0; c < 64; c++) {
            float zc = s_z[p * 65 + c];
#pragma unroll
            for (int jj = 0; jj < 8; jj++)
                dot[jj] += zc * s_cb[(j + 8 * jj) * 65 + c];
        }
#pragma unroll
        for (int jj = 0; jj < 8; jj++) {
            int k = chunk * 64 + j + 8 * jj;
            float d = g_e2[k] - 2.f * dot[jj];
            if (d < best_d || (d == best_d && k < best_k)) { best_d = d; best_k = k; }
        }
    }

    // reduce over the 8 threads sharing a position (contiguous lanes)
#pragma unroll
    for (int off = 4; off; off >>= 1) {
        float od = __shfl_down_sync(0xffffffffu, best_d, off);
        int   ok = __shfl_down_sync(0xffffffffu, best_k, off);
        if (od < best_d || (od == best_d && ok < best_k)) { best_d = od; best_k = ok; }
    }
    if (j == 0) { s_bd[p] = best_d; s_bk[p] = best_k; }
    __syncthreads();

    if (tid < 32) g_dmin[pos0 + tid] = s_z2[tid] + s_bd[tid];

    // gather z_q (coalesced along hw)
    {
        int pl = tid & 31, cb8 = tid >> 5;
        float* zqb = g_zq + (size_t)b * 262144;
        int kidx = s_bk[pl];
        for (int cc = 0; cc < 8; cc++) {
            int c = cb8 * 8 + cc;
            zqb[(size_t)c * 4096 + hw0 + pl] = cb[kidx * 64 + c];
        }
    }
}

__global__ void k_loss(float* __restrict__ out_loss)
{
    __shared__ float sm[1024];
    int tid = threadIdx.x;
    float s = 0.f;
    for (int i = tid; i < 32768; i += 1024) s += g_dmin[i];
    sm[tid] = s;
    __syncthreads();
    for (int off = 512; off; off >>= 1) {
        if (tid < off) sm[tid] += sm[tid + off];
        __syncthreads();
    }
    if (tid == 0) out_loss[0] = sm[0] * (1.25f / 2097152.f);
}

// ---------------- launch ----------------
extern "C" void kernel_launch(void* const* d_in, const int* in_sizes, int n_in,
                              void* d_out, int out_size)
{
    const float* x   = (const float*)d_in[0];
    const float* ew1 = (const float*)d_in[1];
    const float* eb1 = (const float*)d_in[2];
    const float* ew2 = (const float*)d_in[3];
    const float* eb2 = (const float*)d_in[4];
    const float* ew3 = (const float*)d_in[5];
    const float* eb3 = (const float*)d_in[6];
    const float* ew4 = (const float*)d_in[7];
    const float* eb4 = (const float*)d_in[8];
    const float* cb  = (const float*)d_in[9];
    const float* dw1 = (const float*)d_in[10];
    const float* db1 = (const float*)d_in[11];
    const float* tw1 = (const float*)d_in[12];
    const float* tb1 = (const float*)d_in[13];
    const float* tw2 = (const float*)d_in[14];
    const float* tb2 = (const float*)d_in[15];
    const float* tw3 = (const float*)d_in[16];
    const float* tb3 = (const float*)d_in[17];
    float* out = (float*)d_out;

    // encoder
    k_e2<<<1, 512>>>(cb);
    k_conv1<<<2048, 256>>>(x, ew1, eb1);                                  // x -> a1
    k_conv4x4s2<<<dim3(4, 4, 64), 256>>>(1, ew2, eb2, 2, 256, 256);       // a1 -> a2
    k_conv4x4s2<<<dim3(2, 2, 64), 256>>>(2, ew3, eb3, 3, 128, 128);       // a2 -> a3
    k_conv3x3<<<dim3(2, 2, 64), 256>>>(3, ew4, eb4, 4, 0);                // a3 -> z

    // vector quantizer
    k_vq<<<1024, 256>>>(cb);                                              // z -> zq, dmin
    k_loss<<<1, 1024>>>(out + (out_size - 1));

    // decoder
    k_conv3x3<<<dim3(2, 2, 64), 256>>>(5, dw1, db1, 6, 1);                // zq -> d1
    k_convt<<<dim3(4, 4, 64), 256>>>(6, tw1, tb1, 2, 64, 64);             // d1 -> a2 (128^2)
    k_convt<<<dim3(8, 8, 64), 256>>>(2, tw2, tb2, 1, 128, 128);           // a2 -> a1 (256^2)
    k_convt_out<<<dim3(16, 16, 8), 256>>>(tw3, tb3, out);                 // a1 -> x_hat
}

// round 4
// speedup vs baseline: 2.1676x; 2.1676x over previous
#include <cuda_runtime.h>
#include <math.h>
#include <float.h>
#include <stdint.h>

// ---------------- scratch ----------------
__device__ float g_a1[33554432];
__device__ float g_a2[8388608];
__device__ float g_a3[2097152];
__device__ float g_z [2097152];
__device__ float g_zq[2097152];
__device__ float g_d1[2097152];
__device__ float g_dmin[32768];
__device__ float g_e2[512];
// prepped weights [tap][ci][co]
__device__ float g_pw2[16*64*64];
__device__ float g_pw3[16*64*64];
__device__ float g_pe4[9*64*64];
__device__ float g_pd1[9*64*64];
__device__ float g_pt1[16*64*64];
__device__ float g_pt2[16*64*64];

__device__ __forceinline__ float* g_buf(int s) {
    switch (s) {
        case 1: return g_a1; case 2: return g_a2; case 3: return g_a3;
        case 4: return g_z;  case 5: return g_zq; case 6: return g_d1;
    }
    return nullptr;
}
__device__ __forceinline__ float* g_pbuf(int s) {
    switch (s) {
        case 1: return g_pw2; case 2: return g_pw3; case 3: return g_pe4;
        case 4: return g_pd1; case 5: return g_pt1; case 6: return g_pt2;
    }
    return nullptr;
}

// ---------------- f32x2 + cp.async helpers ----------------
__device__ __forceinline__ unsigned long long pk2(float x, float y) {
    unsigned long long r;
    asm("mov.b64 %0, {%1,%2};" : "=l"(r) : "f"(x), "f"(y));
    return r;
}
__device__ __forceinline__ float2 upk2(unsigned long long v) {
    float2 r;
    asm("mov.b64 {%0,%1}, %2;" : "=f"(r.x), "=f"(r.y) : "l"(v));
    return r;
}
__device__ __forceinline__ void ffma2(unsigned long long& d, unsigned long long a,
                                      unsigned long long b) {
    asm("fma.rn.f32x2 %0, %1, %2, %3;" : "=l"(d) : "l"(a), "l"(b), "l"(d));
}
__device__ __forceinline__ void cp4(uint32_t dst, const float* src, bool p) {
    int sz = p ? 4 : 0;
    asm volatile("cp.async.ca.shared.global [%0], [%1], 4, %2;\n"
                 :: "r"(dst), "l"(src), "r"(sz));
}
__device__ __forceinline__ void cp16(uint32_t dst, const float* src) {
    asm volatile("cp.async.ca.shared.global [%0], [%1], 16;\n" :: "r"(dst), "l"(src));
}
__device__ __forceinline__ void cp_commit() { asm volatile("cp.async.commit_group;"); }
__device__ __forceinline__ void cp_wait0()  { asm volatile("cp.async.wait_group 0;"); }

// ---------------- weight prep ----------------
__global__ void k_prep_oihw(const float* __restrict__ w, int taps, int dsel)
{
    float* dst = g_pbuf(dsel);
    int bi = blockIdx.x;                 // ci*taps + tap
    int ci = bi / taps, tap = bi - ci * taps;
    int co = threadIdx.x;
    dst[(tap * 64 + ci) * 64 + co] = w[(co * 64 + ci) * taps + tap];
}
__global__ void k_prep_t(const float* __restrict__ w, int dsel)
{
    float* dst = g_pbuf(dsel);
    int bi = blockIdx.x;                 // cls(4) tap(4) ci(64)
    int ci = bi & 63, tap = (bi >> 6) & 3, cls = bi >> 8;
    int dy = cls >> 1, dx = cls & 1, a = tap >> 1, bb = tap & 1;
    int ky = 1 - dy + 2 * a, kx = 1 - dx + 2 * bb;
    int co = threadIdx.x;
    dst[((cls * 4 + tap) * 64 + ci) * 64 + co] = w[(ci * 64 + co) * 16 + ky * 4 + kx];
}

// ---------------- GEMM core: 32 ci, 8pos x 8co per thread ----------------
__device__ __forceinline__ void compute32(const float* sA, const float* sB,
                                          int pg, int cg, unsigned long long acc[8][4])
{
#pragma unroll 8
    for (int ci = 0; ci < 32; ci++) {
        ulonglong2 aL = *(const ulonglong2*)(sA + ci * 128 + pg * 8);
        ulonglong2 aH = *(const ulonglong2*)(sA + ci * 128 + pg * 8 + 4);
        float4 w0 = *(const float4*)(sB + ci * 64 + cg * 8);
        float4 w1 = *(const float4*)(sB + ci * 64 + cg * 8 + 4);
        unsigned long long W[8] = {
            pk2(w0.x, w0.x), pk2(w0.y, w0.y), pk2(w0.z, w0.z), pk2(w0.w, w0.w),
            pk2(w1.x, w1.x), pk2(w1.y, w1.y), pk2(w1.z, w1.z), pk2(w1.w, w1.w)};
#pragma unroll
        for (int co = 0; co < 8; co++) {
            ffma2(acc[co][0], aL.x, W[co]);
            ffma2(acc[co][1], aL.y, W[co]);
            ffma2(acc[co][2], aH.x, W[co]);
            ffma2(acc[co][3], aH.y, W[co]);
        }
    }
}

// ---------------- k4 s2 p1 conv, 64->64, relu ----------------
__global__ __launch_bounds__(128, 3) void k_gconv4(int in_sel, int wsel,
    const float* __restrict__ bias, int out_sel, int Hin, int Win)
{
    __shared__ __align__(16) float sAa[2][32 * 128];
    __shared__ __align__(16) float sBa[2][32 * 64];
    const float* in = g_buf(in_sel);
    const float* wp = g_pbuf(wsel);
    float* out = g_buf(out_sel);
    const int Hout = Hin >> 1, Wout = Win >> 1;
    const int tid = threadIdx.x, pg = tid & 15, cg = tid >> 4;
    const int b = blockIdx.y;
    int p_oy, p_ox;
    if (Wout == 128) { p_oy = blockIdx.x;                 p_ox = tid; }
    else             { p_oy = blockIdx.x * 2 + (tid >> 6); p_ox = tid & 63; }
    const size_t HW = (size_t)Hin * Win;
    const float* inb = in + (size_t)b * 64 * HW;
    uint32_t sA0 = (uint32_t)__cvta_generic_to_shared(&sAa[0][0]);
    uint32_t sB0 = (uint32_t)__cvta_generic_to_shared(&sBa[0][0]);

    unsigned long long acc[8][4];
#pragma unroll
    for (int i = 0; i < 8; i++)
#pragma unroll
        for (int j = 0; j < 4; j++) acc[i][j] = 0ull;

    auto stage = [&](int s, int buf) {
        int tap = s >> 1, chunk = s & 1;
        int ky = tap >> 2, kx = tap & 3;
        int iy = 2 * p_oy + ky - 1, ix = 2 * p_ox + kx - 1;
        bool ok = (unsigned)iy < (unsigned)Hin && (unsigned)ix < (unsigned)Win;
        const float* base = inb + (size_t)chunk * 32 * HW;
        const float* src = ok ? base + (size_t)iy * Win + ix : base;
        uint32_t dA = sA0 + buf * (32 * 128 * 4) + tid * 4;
#pragma unroll
        for (int j = 0; j < 32; j++) cp4(dA + j * 512, src + (size_t)j * HW, ok);
        const float* wsrc = wp + ((size_t)tap * 64 + chunk * 32) * 64;
        uint32_t dB = sB0 + buf * (32 * 64 * 4);
#pragma unroll
        for (int j = 0; j < 4; j++) cp16(dB + (j * 128 + tid) * 16, wsrc + (j * 128 + tid) * 4);
    };

    stage(0, 0); cp_commit(); cp_wait0(); __syncthreads();
    for (int s = 0; s < 32; s++) {
        int buf = s & 1;
        if (s + 1 < 32) { stage(s + 1, buf ^ 1); cp_commit(); }
        compute32(sAa[buf], sBa[buf], pg, cg, acc);
        if (s + 1 < 32) cp_wait0();
        __syncthreads();
    }

    int q_oy, q_ox;
    if (Wout == 128) { q_oy = blockIdx.x;                  q_ox = pg * 8; }
    else             { q_oy = blockIdx.x * 2 + (pg >> 3);  q_ox = (pg & 7) * 8; }
#pragma unroll
    for (int co = 0; co < 8; co++) {
        int c = cg * 8 + co;
        float bv = bias[c];
        float2 u0 = upk2(acc[co][0]), u1 = upk2(acc[co][1]);
        float2 u2 = upk2(acc[co][2]), u3 = upk2(acc[co][3]);
        float4 r0 = make_float4(fmaxf(u0.x + bv, 0.f), fmaxf(u0.y + bv, 0.f),
                                fmaxf(u1.x + bv, 0.f), fmaxf(u1.y + bv, 0.f));
        float4 r1 = make_float4(fmaxf(u2.x + bv, 0.f), fmaxf(u2.y + bv, 0.f),
                                fmaxf(u3.x + bv, 0.f), fmaxf(u3.y + bv, 0.f));
        float* op = out + (((size_t)b * 64 + c) * Hout + q_oy) * Wout + q_ox;
        *(float4*)op = r0; *(float4*)(op + 4) = r1;
    }
}

// ---------------- k3 s1 p1 conv on 64x64, 64->64 ----------------
__global__ __launch_bounds__(128, 3) void k_gconv3(int in_sel, int wsel,
    const float* __restrict__ bias, int out_sel, int do_relu)
{
    __shared__ __align__(16) float sAa[2][32 * 128];
    __shared__ __align__(16) float sBa[2][32 * 64];
    const float* in = g_buf(in_sel);
    const float* wp = g_pbuf(wsel);
    float* out = g_buf(out_sel);
    const int tid = threadIdx.x, pg = tid & 15, cg = tid >> 4;
    const int b = blockIdx.y;
    const int p_oy = blockIdx.x * 2 + (tid >> 6), p_ox = tid & 63;
    const float* inb = in + (size_t)b * 64 * 4096;
    uint32_t sA0 = (uint32_t)__cvta_generic_to_shared(&sAa[0][0]);
    uint32_t sB0 = (uint32_t)__cvta_generic_to_shared(&sBa[0][0]);

    unsigned long long acc[8][4];
#pragma unroll
    for (int i = 0; i < 8; i++)
#pragma unroll
        for (int j = 0; j < 4; j++) acc[i][j] = 0ull;

    auto stage = [&](int s, int buf) {
        int tap = s >> 1, chunk = s & 1;
        int ky = tap / 3, kx = tap - ky * 3;
        int iy = p_oy + ky - 1, ix = p_ox + kx - 1;
        bool ok = (unsigned)iy < 64u && (unsigned)ix < 64u;
        const float* base = inb + (size_t)chunk * 32 * 4096;
        const float* src = ok ? base + iy * 64 + ix : base;
        uint32_t dA = sA0 + buf * (32 * 128 * 4) + tid * 4;
#pragma unroll
        for (int j = 0; j < 32; j++) cp4(dA + j * 512, src + j * 4096, ok);
        const float* wsrc = wp + ((size_t)tap * 64 + chunk * 32) * 64;
        uint32_t dB = sB0 + buf * (32 * 64 * 4);
#pragma unroll
        for (int j = 0; j < 4; j++) cp16(dB + (j * 128 + tid) * 16, wsrc + (j * 128 + tid) * 4);
    };

    stage(0, 0); cp_commit(); cp_wait0(); __syncthreads();
    for (int s = 0; s < 18; s++) {
        int buf = s & 1;
        if (s + 1 < 18) { stage(s + 1, buf ^ 1); cp_commit(); }
        compute32(sAa[buf], sBa[buf], pg, cg, acc);
        if (s + 1 < 18) cp_wait0();
        __syncthreads();
    }

    const int q_oy = blockIdx.x * 2 + (pg >> 3), q_ox = (pg & 7) * 8;
#pragma unroll
    for (int co = 0; co < 8; co++) {
        int c = cg * 8 + co;
        float bv = bias[c];
        float2 u0 = upk2(acc[co][0]), u1 = upk2(acc[co][1]);
        float2 u2 = upk2(acc[co][2]), u3 = upk2(acc[co][3]);
        float r[8] = {u0.x + bv, u0.y + bv, u1.x + bv, u1.y + bv,
                      u2.x + bv, u2.y + bv, u3.x + bv, u3.y + bv};
        if (do_relu)
#pragma unroll
            for (int i = 0; i < 8; i++) r[i] = fmaxf(r[i], 0.f);
        float* op = out + (((size_t)b * 64 + c) * 64 + q_oy) * 64 + q_ox;
        *(float4*)op = make_float4(r[0], r[1], r[2], r[3]);
        *(float4*)(op + 4) = make_float4(r[4], r[5], r[6], r[7]);
    }
}

// ---------------- convT k4 s2 p1 via parity classes, 64->64, relu ------------
__global__ __launch_bounds__(128, 3) void k_gconvt(int in_sel, int wsel,
    const float* __restrict__ bias, int out_sel, int Hin, int Win)
{
    __shared__ __align__(16) float sAa[2][32 * 128];
    __shared__ __align__(16) float sBa[2][32 * 64];
    const float* in = g_buf(in_sel);
    const float* wp = g_pbuf(wsel);
    float* out = g_buf(out_sel);
    const int Hout = Hin << 1, Wout = Win << 1;
    const int tid = threadIdx.x, pg = tid & 15, cg = tid >> 4;
    const int b = blockIdx.y;
    const int cls = blockIdx.z, dy = cls >> 1, dx = cls & 1;
    int p_y, p_x;
    if (Win == 128) { p_y = blockIdx.x;                 p_x = tid; }
    else            { p_y = blockIdx.x * 2 + (tid >> 6); p_x = tid & 63; }
    const size_t HW = (size_t)Hin * Win;
    const float* inb = in + (size_t)b * 64 * HW;
    uint32_t sA0 = (uint32_t)__cvta_generic_to_shared(&sAa[0][0]);
    uint32_t sB0 = (uint32_t)__cvta_generic_to_shared(&sBa[0][0]);

    unsigned long long acc[8][4];
#pragma unroll
    for (int i = 0; i < 8; i++)
#pragma unroll
        for (int j = 0; j < 4; j++) acc[i][j] = 0ull;

    auto stage = [&](int s, int buf) {
        int tap = s >> 1, chunk = s & 1;
        int a = tap >> 1, bb = tap & 1;
        int iy = p_y + dy - a, ix = p_x + dx - bb;
        bool ok = (unsigned)iy < (unsigned)Hin && (unsigned)ix < (unsigned)Win;
        const float* base = inb + (size_t)chunk * 32 * HW;
        const float* src = ok ? base + (size_t)iy * Win + ix : base;
        uint32_t dA = sA0 + buf * (32 * 128 * 4) + tid * 4;
#pragma unroll
        for (int j = 0; j < 32; j++) cp4(dA + j * 512, src + (size_t)j * HW, ok);
        const float* wsrc = wp + ((size_t)(cls * 4 + tap) * 64 + chunk * 32) * 64;
        uint32_t dB = sB0 + buf * (32 * 64 * 4);
#pragma unroll
        for (int j = 0; j < 4; j++) cp16(dB + (j * 128 + tid) * 16, wsrc + (j * 128 + tid) * 4);
    };

    stage(0, 0); cp_commit(); cp_wait0(); __syncthreads();
    for (int s = 0; s < 8; s++) {
        int buf = s & 1;
        if (s + 1 < 8) { stage(s + 1, buf ^ 1); cp_commit(); }
        compute32(sAa[buf], sBa[buf], pg, cg, acc);
        if (s + 1 < 8) cp_wait0();
        __syncthreads();
    }

    int row, x0;
    if (Win == 128) { row = blockIdx.x;                 x0 = pg * 8; }
    else            { row = blockIdx.x * 2 + (pg >> 3); x0 = (pg & 7) * 8; }
    const int oy = 2 * row + dy;
#pragma unroll
    for (int co = 0; co < 8; co++) {
        int c = cg * 8 + co;
        float bv = bias[c];
        float2 u0 = upk2(acc[co][0]), u1 = upk2(acc[co][1]);
        float2 u2 = upk2(acc[co][2]), u3 = upk2(acc[co][3]);
        float r[8] = {u0.x + bv, u0.y + bv, u1.x + bv, u1.y + bv,
                      u2.x + bv, u2.y + bv, u3.x + bv, u3.y + bv};
        float* op = out + (((size_t)b * 64 + c) * Hout + oy) * Wout + 2 * x0 + dx;
#pragma unroll
        for (int i = 0; i < 8; i++) op[2 * i] = fmaxf(r[i], 0.f);
    }
}

// ---------------- conv1: 1->64 k4 s2 p1, relu ----------------
__global__ void k_conv1(const float* __restrict__ x, const float* __restrict__ w,
                        const float* __restrict__ bias)
{
    __shared__ float sw[1024];
    __shared__ float sb[64];
    const int tid = threadIdx.x;
    for (int i = tid; i < 1024; i += 256) sw[i] = w[i];
    if (tid < 64) sb[tid] = bias[tid];
    __syncthreads();
    const int gid = blockIdx.x * 256 + tid;
    const int ox = gid & 255, oy = (gid >> 8) & 255, b = gid >> 16;
    const int iy0 = oy * 2 - 1, ix0 = ox * 2 - 1;
    const float* xb = x + (size_t)b * 262144;
    float v[16];
#pragma unroll
    for (int ky = 0; ky < 4; ky++)
#pragma unroll
        for (int kx = 0; kx < 4; kx++) {
            int iy = iy0 + ky, ix = ix0 + kx;
            float t = 0.f;
            if ((unsigned)iy < 512u && (unsigned)ix < 512u) t = xb[iy * 512 + ix];
            v[ky * 4 + kx] = t;
        }
    float* ob = g_a1 + (size_t)b * 64 * 65536 + oy * 256 + ox;
#pragma unroll 4
    for (int co = 0; co < 64; co++) {
        float a = sb[co];
#pragma unroll
        for (int t = 0; t < 16; t++) a += v[t] * sw[co * 16 + t];
        ob[(size_t)co * 65536] = fmaxf(a, 0.f);
    }
}

// ---------------- convT3: 64->1, sigmoid, 256->512 ----------------
__global__ void k_convt_out(const float* __restrict__ w,
                            const float* __restrict__ bias, float* __restrict__ out)
{
    __shared__ float s_in[18 * 19];
    __shared__ float s_w[16];
    const int tid = threadIdx.x;
    const int tx = tid & 15, ty = tid >> 4;
    const int b = blockIdx.z;
    const int oy0 = blockIdx.y << 5, ox0 = blockIdx.x << 5;
    const int iy0 = (oy0 >> 1) - 1, ix0 = (ox0 >> 1) - 1;
    const float* inb = g_a1 + (size_t)b * 64 * 65536;
    float acc[4] = {0.f, 0.f, 0.f, 0.f};
    for (int ci = 0; ci < 64; ci++) {
        __syncthreads();
        const float* ic = inb + (size_t)ci * 65536;
        for (int i = tid; i < 18 * 18; i += 256) {
            int r = i / 18, c = i - r * 18;
            int iy = iy0 + r, ix = ix0 + c;
            float t = 0.f;
            if ((unsigned)iy < 256u && (unsigned)ix < 256u) t = ic[(iy << 8) + ix];
            s_in[r * 19 + c] = t;
        }
        if (tid < 16) s_w[tid] = w[ci * 16 + tid];
        __syncthreads();
        float v[3][3];
#pragma unroll
        for (int r = 0; r < 3; r++)
#pragma unroll
            for (int c = 0; c < 3; c++) v[r][c] = s_in[(ty + r) * 19 + tx + c];
#pragma unroll
        for (int ky = 0; ky < 4; ky++) {
            const int dy = 1 - (ky & 1), rr = (4 - ky) >> 1;
#pragma unroll
            for (int kx = 0; kx < 4; kx++) {
                const int dx = 1 - (kx & 1), cc = (4 - kx) >> 1;
                acc[dy * 2 + dx] += v[rr][cc] * s_w[(ky << 2) + kx];
            }
        }
    }
    float bv = bias[0];
#pragma unroll
    for (int dy = 0; dy < 2; dy++)
#pragma unroll
        for (int dx = 0; dx < 2; dx++) {
            float s = acc[dy * 2 + dx] + bv;
            s = 1.f / (1.f + expf(-s));
            out[((size_t)b * 512 + oy0 + 2 * ty + dy) * 512 + ox0 + 2 * tx + dx] = s;
        }
}

// ---------------- VQ ----------------
__global__ void k_e2(const float* __restrict__ cb)
{
    int k = threadIdx.x;
    float s = 0.f;
    for (int c = 0; c < 64; c++) { float v = cb[k * 64 + c]; s += v * v; }
    g_e2[k] = s;
}

__global__ void k_vq(const float* __restrict__ cb)
{
    __shared__ float s_z[32 * 65];
    __shared__ float s_cb[64 * 65];
    __shared__ float s_z2[32];
    __shared__ float s_bd[32];
    __shared__ int   s_bk[32];
    const int tid = threadIdx.x;
    const int pos0 = blockIdx.x * 32;
    const int b = pos0 >> 12, hw0 = pos0 & 4095;
    const float* zb = g_z + (size_t)b * 262144;
    {
        int pl = tid & 31, cb8 = tid >> 5;
        for (int cc = 0; cc < 8; cc++) {
            int c = cb8 * 8 + cc;
            s_z[pl * 65 + c] = zb[(size_t)c * 4096 + hw0 + pl];
        }
    }
    __syncthreads();
    if (tid < 32) {
        float s = 0.f;
        for (int c = 0; c < 64; c++) { float t = s_z[tid * 65 + c]; s += t * t; }
        s_z2[tid] = s;
    }
    const int j = tid & 7, p = tid >> 3;
    float best_d = FLT_MAX; int best_k = 0;
    for (int chunk = 0; chunk < 8; chunk++) {
        __syncthreads();
        for (int i = tid; i < 4096; i += 256) {
            int code = i >> 6, c = i & 63;
            s_cb[code * 65 + c] = cb[chunk * 4096 + i];
        }
        __syncthreads();
        float dot[8];
#pragma unroll
        for (int jj = 0; jj < 8; jj++) dot[jj] = 0.f;
        for (int c = 0; c < 64; c++) {
            float zc = s_z[p * 65 + c];
#pragma unroll
            for (int jj = 0; jj < 8; jj++) dot[jj] += zc * s_cb[(j + 8 * jj) * 65 + c];
        }
#pragma unroll
        for (int jj = 0; jj < 8; jj++) {
            int k = chunk * 64 + j + 8 * jj;
            float d = g_e2[k] - 2.f * dot[jj];
            if (d < best_d || (d == best_d && k < best_k)) { best_d = d; best_k = k; }
        }
    }
#pragma unroll
    for (int off = 4; off; off >>= 1) {
        float od = __shfl_down_sync(0xffffffffu, best_d, off);
        int   ok = __shfl_down_sync(0xffffffffu, best_k, off);
        if (od < best_d || (od == best_d && ok < best_k)) { best_d = od; best_k = ok; }
    }
    if (j == 0) { s_bd[p] = best_d; s_bk[p] = best_k; }
    __syncthreads();
    if (tid < 32) g_dmin[pos0 + tid] = s_z2[tid] + s_bd[tid];
    {
        int pl = tid & 31, cb8 = tid >> 5;
        float* zqb = g_zq + (size_t)b * 262144;
        int kidx = s_bk[pl];
        for (int cc = 0; cc < 8; cc++) {
            int c = cb8 * 8 + cc;
            zqb[(size_t)c * 4096 + hw0 + pl] = cb[kidx * 64 + c];
        }
    }
}

__global__ void k_loss(float* __restrict__ out_loss)
{
    __shared__ float sm[1024];
    int tid = threadIdx.x;
    float s = 0.f;
    for (int i = tid; i < 32768; i += 1024) s += g_dmin[i];
    sm[tid] = s;
    __syncthreads();
    for (int off = 512; off; off >>= 1) {
        if (tid < off) sm[tid] += sm[tid + off];
        __syncthreads();
    }
    if (tid == 0) out_loss[0] = sm[0] * (1.25f / 2097152.f);
}

// ---------------- launch ----------------
extern "C" void kernel_launch(void* const* d_in, const int* in_sizes, int n_in,
                              void* d_out, int out_size)
{
    const float* x   = (const float*)d_in[0];
    const float* ew1 = (const float*)d_in[1];
    const float* eb1 = (const float*)d_in[2];
    const float* ew2 = (const float*)d_in[3];
    const float* eb2 = (const float*)d_in[4];
    const float* ew3 = (const float*)d_in[5];
    const float* eb3 = (const float*)d_in[6];
    const float* ew4 = (const float*)d_in[7];
    const float* eb4 = (const float*)d_in[8];
    const float* cb  = (const float*)d_in[9];
    const float* dw1 = (const float*)d_in[10];
    const float* db1 = (const float*)d_in[11];
    const float* tw1 = (const float*)d_in[12];
    const float* tb1 = (const float*)d_in[13];
    const float* tw2 = (const float*)d_in[14];
    const float* tb2 = (const float*)d_in[15];
    const float* tw3 = (const float*)d_in[16];
    const float* tb3 = (const float*)d_in[17];
    float* out = (float*)d_out;

    // weight prep
    k_prep_oihw<<<64 * 16, 64>>>(ew2, 16, 1);
    k_prep_oihw<<<64 * 16, 64>>>(ew3, 16, 2);
    k_prep_oihw<<<64 * 9, 64>>>(ew4, 9, 3);
    k_prep_oihw<<<64 * 9, 64>>>(dw1, 9, 4);
    k_prep_t<<<1024, 64>>>(tw1, 5);
    k_prep_t<<<1024, 64>>>(tw2, 6);
    k_e2<<<1, 512>>>(cb);

    // encoder
    k_conv1<<<2048, 256>>>(x, ew1, eb1);                            // x  -> a1
    k_gconv4<<<dim3(128, 8), 128>>>(1, 1, eb2, 2, 256, 256);        // a1 -> a2
    k_gconv4<<<dim3(32, 8), 128>>>(2, 2, eb3, 3, 128, 128);         // a2 -> a3
    k_gconv3<<<dim3(32, 8), 128>>>(3, 3, eb4, 4, 0);                // a3 -> z

    // VQ
    k_vq<<<1024, 256>>>(cb);
    k_loss<<<1, 1024>>>(out + (out_size - 1));

    // decoder
    k_gconv3<<<dim3(32, 8), 128>>>(5, 4, db1, 6, 1);                // zq -> d1
    k_gconvt<<<dim3(32, 8, 4), 128>>>(6, 5, tb1, 2, 64, 64);        // d1 -> a2
    k_gconvt<<<dim3(128, 8, 4), 128>>>(2, 6, tb2, 1, 128, 128);     // a2 -> a1
    k_convt_out<<<dim3(16, 16, 8), 256>>>(tw3, tb3, out);           // a1 -> out
}

// round 5
// speedup vs baseline: 2.1677x; 1.0001x over previous
#include <cuda_runtime.h>
#include <math.h>
#include <float.h>
#include <stdint.h>

// ---------------- scratch ----------------
__device__ float g_a1[33554432];
__device__ float g_a2[8388608];
__device__ float g_a3[2097152];
__device__ float g_z [2097152];
__device__ float g_zq[2097152];
__device__ float g_d1[2097152];
__device__ float g_dmin[32768];
__device__ float g_e2[512];
// prepped weights [tap][ci][co]
__device__ float g_pw2[16*64*64];
__device__ float g_pw3[16*64*64];
__device__ float g_pe4[9*64*64];
__device__ float g_pd1[9*64*64];
__device__ float g_pt1[16*64*64];
__device__ float g_pt2[16*64*64];

__device__ __forceinline__ float* g_buf(int s) {
    switch (s) {
        case 1: return g_a1; case 2: return g_a2; case 3: return g_a3;
        case 4: return g_z;  case 5: return g_zq; case 6: return g_d1;
    }
    return nullptr;
}
__device__ __forceinline__ float* g_pbuf(int s) {
    switch (s) {
        case 1: return g_pw2; case 2: return g_pw3; case 3: return g_pe4;
        case 4: return g_pd1; case 5: return g_pt1; case 6: return g_pt2;
    }
    return nullptr;
}

// ---------------- f32x2 + cp.async helpers ----------------
__device__ __forceinline__ unsigned long long pk2(float x, float y) {
    unsigned long long r;
    asm("mov.b64 %0, {%1,%2};" : "=l"(r) : "f"(x), "f"(y));
    return r;
}
__device__ __forceinline__ float2 upk2(unsigned long long v) {
    float2 r;
    asm("mov.b64 {%0,%1}, %2;" : "=f"(r.x), "=f"(r.y) : "l"(v));
    return r;
}
__device__ __forceinline__ void ffma2(unsigned long long& d, unsigned long long a,
                                      unsigned long long b) {
    asm("fma.rn.f32x2 %0, %1, %2, %3;" : "=l"(d) : "l"(a), "l"(b), "l"(d));
}
__device__ __forceinline__ void cp4(uint32_t dst, const float* src, bool p) {
    int sz = p ? 4 : 0;
    asm volatile("cp.async.ca.shared.global [%0], [%1], 4, %2;\n"
                 :: "r"(dst), "l"(src), "r"(sz));
}
__device__ __forceinline__ void cp16(uint32_t dst, const float* src) {
    asm volatile("cp.async.ca.shared.global [%0], [%1], 16;\n" :: "r"(dst), "l"(src));
}
__device__ __forceinline__ void cp_commit() { asm volatile("cp.async.commit_group;"); }
__device__ __forceinline__ void cp_wait0()  { asm volatile("cp.async.wait_group 0;"); }

// ---------------- weight prep ----------------
__global__ void k_prep_oihw(const float* __restrict__ w, int taps, int dsel)
{
    float* dst = g_pbuf(dsel);
    int bi = blockIdx.x;                 // ci*taps + tap
    int ci = bi / taps, tap = bi - ci * taps;
    int co = threadIdx.x;
    dst[(tap * 64 + ci) * 64 + co] = w[(co * 64 + ci) * taps + tap];
}
__global__ void k_prep_t(const float* __restrict__ w, int dsel)
{
    float* dst = g_pbuf(dsel);
    int bi = blockIdx.x;                 // cls(4) tap(4) ci(64)
    int ci = bi & 63, tap = (bi >> 6) & 3, cls = bi >> 8;
    int dy = cls >> 1, dx = cls & 1, a = tap >> 1, bb = tap & 1;
    int ky = 1 - dy + 2 * a, kx = 1 - dx + 2 * bb;
    int co = threadIdx.x;
    dst[((cls * 4 + tap) * 64 + ci) * 64 + co] = w[(ci * 64 + co) * 16 + ky * 4 + kx];
}

// ---------------- GEMM core: 32 ci, 8pos x 8co per thread ----------------
__device__ __forceinline__ void compute32(const float* sA, const float* sB,
                                          int pg, int cg, unsigned long long acc[8][4])
{
#pragma unroll 8
    for (int ci = 0; ci < 32; ci++) {
        ulonglong2 aL = *(const ulonglong2*)(sA + ci * 128 + pg * 8);
        ulonglong2 aH = *(const ulonglong2*)(sA + ci * 128 + pg * 8 + 4);
        float4 w0 = *(const float4*)(sB + ci * 64 + cg * 8);
        float4 w1 = *(const float4*)(sB + ci * 64 + cg * 8 + 4);
        unsigned long long W[8] = {
            pk2(w0.x, w0.x), pk2(w0.y, w0.y), pk2(w0.z, w0.z), pk2(w0.w, w0.w),
            pk2(w1.x, w1.x), pk2(w1.y, w1.y), pk2(w1.z, w1.z), pk2(w1.w, w1.w)};
#pragma unroll
        for (int co = 0; co < 8; co++) {
            ffma2(acc[co][0], aL.x, W[co]);
            ffma2(acc[co][1], aL.y, W[co]);
            ffma2(acc[co][2], aH.x, W[co]);
            ffma2(acc[co][3], aH.y, W[co]);
        }
    }
}

// ---------------- k4 s2 p1 conv, 64->64, relu ----------------
__global__ __launch_bounds__(128, 3) void k_gconv4(int in_sel, int wsel,
    const float* __restrict__ bias, int out_sel, int Hin, int Win)
{
    __shared__ __align__(16) float sAa[2][32 * 128];
    __shared__ __align__(16) float sBa[2][32 * 64];
    const float* in = g_buf(in_sel);
    const float* wp = g_pbuf(wsel);
    float* out = g_buf(out_sel);
    const int Hout = Hin >> 1, Wout = Win >> 1;
    const int tid = threadIdx.x, pg = tid & 15, cg = tid >> 4;
    const int b = blockIdx.y;
    int p_oy, p_ox;
    if (Wout == 128) { p_oy = blockIdx.x;                 p_ox = tid; }
    else             { p_oy = blockIdx.x * 2 + (tid >> 6); p_ox = tid & 63; }
    const size_t HW = (size_t)Hin * Win;
    const float* inb = in + (size_t)b * 64 * HW;
    uint32_t sA0 = (uint32_t)__cvta_generic_to_shared(&sAa[0][0]);
    uint32_t sB0 = (uint32_t)__cvta_generic_to_shared(&sBa[0][0]);

    unsigned long long acc[8][4];
#pragma unroll
    for (int i = 0; i < 8; i++)
#pragma unroll
        for (int j = 0; j < 4; j++) acc[i][j] = 0ull;

    auto stage = [&](int s, int buf) {
        int tap = s >> 1, chunk = s & 1;
        int ky = tap >> 2, kx = tap & 3;
        int iy = 2 * p_oy + ky - 1, ix = 2 * p_ox + kx - 1;
        bool ok = (unsigned)iy < (unsigned)Hin && (unsigned)ix < (unsigned)Win;
        const float* base = inb + (size_t)chunk * 32 * HW;
        const float* src = ok ? base + (size_t)iy * Win + ix : base;
        uint32_t dA = sA0 + buf * (32 * 128 * 4) + tid * 4;
#pragma unroll
        for (int j = 0; j < 32; j++) cp4(dA + j * 512, src + (size_t)j * HW, ok);
        const float* wsrc = wp + ((size_t)tap * 64 + chunk * 32) * 64;
        uint32_t dB = sB0 + buf * (32 * 64 * 4);
#pragma unroll
        for (int j = 0; j < 4; j++) cp16(dB + (j * 128 + tid) * 16, wsrc + (j * 128 + tid) * 4);
    };

    stage(0, 0); cp_commit(); cp_wait0(); __syncthreads();
    for (int s = 0; s < 32; s++) {
        int buf = s & 1;
        if (s + 1 < 32) { stage(s + 1, buf ^ 1); cp_commit(); }
        compute32(sAa[buf], sBa[buf], pg, cg, acc);
        if (s + 1 < 32) cp_wait0();
        __syncthreads();
    }

    int q_oy, q_ox;
    if (Wout == 128) { q_oy = blockIdx.x;                  q_ox = pg * 8; }
    else             { q_oy = blockIdx.x * 2 + (pg >> 3);  q_ox = (pg & 7) * 8; }
#pragma unroll
    for (int co = 0; co < 8; co++) {
        int c = cg * 8 + co;
        float bv = bias[c];
        float2 u0 = upk2(acc[co][0]), u1 = upk2(acc[co][1]);
        float2 u2 = upk2(acc[co][2]), u3 = upk2(acc[co][3]);
        float4 r0 = make_float4(fmaxf(u0.x + bv, 0.f), fmaxf(u0.y + bv, 0.f),
                                fmaxf(u1.x + bv, 0.f), fmaxf(u1.y + bv, 0.f));
        float4 r1 = make_float4(fmaxf(u2.x + bv, 0.f), fmaxf(u2.y + bv, 0.f),
                                fmaxf(u3.x + bv, 0.f), fmaxf(u3.y + bv, 0.f));
        float* op = out + (((size_t)b * 64 + c) * Hout + q_oy) * Wout + q_ox;
        *(float4*)op = r0; *(float4*)(op + 4) = r1;
    }
}

// ---------------- k3 s1 p1 conv on 64x64, 64->64 ----------------
__global__ __launch_bounds__(128, 3) void k_gconv3(int in_sel, int wsel,
    const float* __restrict__ bias, int out_sel, int do_relu)
{
    __shared__ __align__(16) float sAa[2][32 * 128];
    __shared__ __align__(16) float sBa[2][32 * 64];
    const float* in = g_buf(in_sel);
    const float* wp = g_pbuf(wsel);
    float* out = g_buf(out_sel);
    const int tid = threadIdx.x, pg = tid & 15, cg = tid >> 4;
    const int b = blockIdx.y;
    const int p_oy = blockIdx.x * 2 + (tid >> 6), p_ox = tid & 63;
    const float* inb = in + (size_t)b * 64 * 4096;
    uint32_t sA0 = (uint32_t)__cvta_generic_to_shared(&sAa[0][0]);
    uint32_t sB0 = (uint32_t)__cvta_generic_to_shared(&sBa[0][0]);

    unsigned long long acc[8][4];
#pragma unroll
    for (int i = 0; i < 8; i++)
#pragma unroll
        for (int j = 0; j < 4; j++) acc[i][j] = 0ull;

    auto stage = [&](int s, int buf) {
        int tap = s >> 1, chunk = s & 1;
        int ky = tap / 3, kx = tap - ky * 3;
        int iy = p_oy + ky - 1, ix = p_ox + kx - 1;
        bool ok = (unsigned)iy < 64u && (unsigned)ix < 64u;
        const float* base = inb + (size_t)chunk * 32 * 4096;
        const float* src = ok ? base + iy * 64 + ix : base;
        uint32_t dA = sA0 + buf * (32 * 128 * 4) + tid * 4;
#pragma unroll
        for (int j = 0; j < 32; j++) cp4(dA + j * 512, src + j * 4096, ok);
        const float* wsrc = wp + ((size_t)tap * 64 + chunk * 32) * 64;
        uint32_t dB = sB0 + buf * (32 * 64 * 4);
#pragma unroll
        for (int j = 0; j < 4; j++) cp16(dB + (j * 128 + tid) * 16, wsrc + (j * 128 + tid) * 4);
    };

    stage(0, 0); cp_commit(); cp_wait0(); __syncthreads();
    for (int s = 0; s < 18; s++) {
        int buf = s & 1;
        if (s + 1 < 18) { stage(s + 1, buf ^ 1); cp_commit(); }
        compute32(sAa[buf], sBa[buf], pg, cg, acc);
        if (s + 1 < 18) cp_wait0();
        __syncthreads();
    }

    const int q_oy = blockIdx.x * 2 + (pg >> 3), q_ox = (pg & 7) * 8;
#pragma unroll
    for (int co = 0; co < 8; co++) {
        int c = cg * 8 + co;
        float bv = bias[c];
        float2 u0 = upk2(acc[co][0]), u1 = upk2(acc[co][1]);
        float2 u2 = upk2(acc[co][2]), u3 = upk2(acc[co][3]);
        float r[8] = {u0.x + bv, u0.y + bv, u1.x + bv, u1.y + bv,
                      u2.x + bv, u2.y + bv, u3.x + bv, u3.y + bv};
        if (do_relu)
#pragma unroll
            for (int i = 0; i < 8; i++) r[i] = fmaxf(r[i], 0.f);
        float* op = out + (((size_t)b * 64 + c) * 64 + q_oy) * 64 + q_ox;
        *(float4*)op = make_float4(r[0], r[1], r[2], r[3]);
        *(float4*)(op + 4) = make_float4(r[4], r[5], r[6], r[7]);
    }
}

// ---------------- convT k4 s2 p1 via parity classes, 64->64, relu ------------
__global__ __launch_bounds__(128, 3) void k_gconvt(int in_sel, int wsel,
    const float* __restrict__ bias, int out_sel, int Hin, int Win)
{
    __shared__ __align__(16) float sAa[2][32 * 128];
    __shared__ __align__(16) float sBa[2][32 * 64];
    const float* in = g_buf(in_sel);
    const float* wp = g_pbuf(wsel);
    float* out = g_buf(out_sel);
    const int Hout = Hin << 1, Wout = Win << 1;
    const int tid = threadIdx.x, pg = tid & 15, cg = tid >> 4;
    const int b = blockIdx.y;
    const int cls = blockIdx.z, dy = cls >> 1, dx = cls & 1;
    int p_y, p_x;
    if (Win == 128) { p_y = blockIdx.x;                 p_x = tid; }
    else            { p_y = blockIdx.x * 2 + (tid >> 6); p_x = tid & 63; }
    const size_t HW = (size_t)Hin * Win;
    const float* inb = in + (size_t)b * 64 * HW;
    uint32_t sA0 = (uint32_t)__cvta_generic_to_shared(&sAa[0][0]);
    uint32_t sB0 = (uint32_t)__cvta_generic_to_shared(&sBa[0][0]);

    unsigned long long acc[8][4];
#pragma unroll
    for (int i = 0; i < 8; i++)
#pragma unroll
        for (int j = 0; j < 4; j++) acc[i][j] = 0ull;

    auto stage = [&](int s, int buf) {
        int tap = s >> 1, chunk = s & 1;
        int a = tap >> 1, bb = tap & 1;
        int iy = p_y + dy - a, ix = p_x + dx - bb;
        bool ok = (unsigned)iy < (unsigned)Hin && (unsigned)ix < (unsigned)Win;
        const float* base = inb + (size_t)chunk * 32 * HW;
        const float* src = ok ? base + (size_t)iy * Win + ix : base;
        uint32_t dA = sA0 + buf * (32 * 128 * 4) + tid * 4;
#pragma unroll
        for (int j = 0; j < 32; j++) cp4(dA + j * 512, src + (size_t)j * HW, ok);
        const float* wsrc = wp + ((size_t)(cls * 4 + tap) * 64 + chunk * 32) * 64;
        uint32_t dB = sB0 + buf * (32 * 64 * 4);
#pragma unroll
        for (int j = 0; j < 4; j++) cp16(dB + (j * 128 + tid) * 16, wsrc + (j * 128 + tid) * 4);
    };

    stage(0, 0); cp_commit(); cp_wait0(); __syncthreads();
    for (int s = 0; s < 8; s++) {
        int buf = s & 1;
        if (s + 1 < 8) { stage(s + 1, buf ^ 1); cp_commit(); }
        compute32(sAa[buf], sBa[buf], pg, cg, acc);
        if (s + 1 < 8) cp_wait0();
        __syncthreads();
    }

    int row, x0;
    if (Win == 128) { row = blockIdx.x;                 x0 = pg * 8; }
    else            { row = blockIdx.x * 2 + (pg >> 3); x0 = (pg & 7) * 8; }
    const int oy = 2 * row + dy;
#pragma unroll
    for (int co = 0; co < 8; co++) {
        int c = cg * 8 + co;
        float bv = bias[c];
        float2 u0 = upk2(acc[co][0]), u1 = upk2(acc[co][1]);
        float2 u2 = upk2(acc[co][2]), u3 = upk2(acc[co][3]);
        float r[8] = {u0.x + bv, u0.y + bv, u1.x + bv, u1.y + bv,
                      u2.x + bv, u2.y + bv, u3.x + bv, u3.y + bv};
        float* op = out + (((size_t)b * 64 + c) * Hout + oy) * Wout + 2 * x0 + dx;
#pragma unroll
        for (int i = 0; i < 8; i++) op[2 * i] = fmaxf(r[i], 0.f);
    }
}

// ---------------- conv1: 1->64 k4 s2 p1, relu ----------------
__global__ void k_conv1(const float* __restrict__ x, const float* __restrict__ w,
                        const float* __restrict__ bias)
{
    __shared__ float sw[1024];
    __shared__ float sb[64];
    const int tid = threadIdx.x;
    for (int i = tid; i < 1024; i += 256) sw[i] = w[i];
    if (tid < 64) sb[tid] = bias[tid];
    __syncthreads();
    const int gid = blockIdx.x * 256 + tid;
    const int ox = gid & 255, oy = (gid >> 8) & 255, b = gid >> 16;
    const int iy0 = oy * 2 - 1, ix0 = ox * 2 - 1;
    const float* xb = x + (size_t)b * 262144;
    float v[16];
#pragma unroll
    for (int ky = 0; ky < 4; ky++)
#pragma unroll
        for (int kx = 0; kx < 4; kx++) {
            int iy = iy0 + ky, ix = ix0 + kx;
            float t = 0.f;
            if ((unsigned)iy < 512u && (unsigned)ix < 512u) t = xb[iy * 512 + ix];
            v[ky * 4 + kx] = t;
        }
    float* ob = g_a1 + (size_t)b * 64 * 65536 + oy * 256 + ox;
#pragma unroll 4
    for (int co = 0; co < 64; co++) {
        float a = sb[co];
#pragma unroll
        for (int t = 0; t < 16; t++) a += v[t] * sw[co * 16 + t];
        ob[(size_t)co * 65536] = fmaxf(a, 0.f);
    }
}

// ---------------- convT3: 64->1, sigmoid, 256->512 ----------------
__global__ void k_convt_out(const float* __restrict__ w,
                            const float* __restrict__ bias, float* __restrict__ out)
{
    __shared__ float s_in[18 * 19];
    __shared__ float s_w[16];
    const int tid = threadIdx.x;
    const int tx = tid & 15, ty = tid >> 4;
    const int b = blockIdx.z;
    const int oy0 = blockIdx.y << 5, ox0 = blockIdx.x << 5;
    const int iy0 = (oy0 >> 1) - 1, ix0 = (ox0 >> 1) - 1;
    const float* inb = g_a1 + (size_t)b * 64 * 65536;
    float acc[4] = {0.f, 0.f, 0.f, 0.f};
    for (int ci = 0; ci < 64; ci++) {
        __syncthreads();
        const float* ic = inb + (size_t)ci * 65536;
        for (int i = tid; i < 18 * 18; i += 256) {
            int r = i / 18, c = i - r * 18;
            int iy = iy0 + r, ix = ix0 + c;
            float t = 0.f;
            if ((unsigned)iy < 256u && (unsigned)ix < 256u) t = ic[(iy << 8) + ix];
            s_in[r * 19 + c] = t;
        }
        if (tid < 16) s_w[tid] = w[ci * 16 + tid];
        __syncthreads();
        float v[3][3];
#pragma unroll
        for (int r = 0; r < 3; r++)
#pragma unroll
            for (int c = 0; c < 3; c++) v[r][c] = s_in[(ty + r) * 19 + tx + c];
#pragma unroll
        for (int ky = 0; ky < 4; ky++) {
            const int dy = 1 - (ky & 1), rr = (4 - ky) >> 1;
#pragma unroll
            for (int kx = 0; kx < 4; kx++) {
                const int dx = 1 - (kx & 1), cc = (4 - kx) >> 1;
                acc[dy * 2 + dx] += v[rr][cc] * s_w[(ky << 2) + kx];
            }
        }
    }
    float bv = bias[0];
#pragma unroll
    for (int dy = 0; dy < 2; dy++)
#pragma unroll
        for (int dx = 0; dx < 2; dx++) {
            float s = acc[dy * 2 + dx] + bv;
            s = 1.f / (1.f + expf(-s));
            out[((size_t)b * 512 + oy0 + 2 * ty + dy) * 512 + ox0 + 2 * tx + dx] = s;
        }
}

// ---------------- VQ ----------------
__global__ void k_e2(const float* __restrict__ cb)
{
    int k = threadIdx.x;
    float s = 0.f;
    for (int c = 0; c < 64; c++) { float v = cb[k * 64 + c]; s += v * v; }
    g_e2[k] = s;
}

__global__ void k_vq(const float* __restrict__ cb)
{
    __shared__ float s_z[32 * 65];
    __shared__ float s_cb[64 * 65];
    __shared__ float s_z2[32];
    __shared__ float s_bd[32];
    __shared__ int   s_bk[32];
    const int tid = threadIdx.x;
    const int pos0 = blockIdx.x * 32;
    const int b = pos0 >> 12, hw0 = pos0 & 4095;
    const float* zb = g_z + (size_t)b * 262144;
    {
        int pl = tid & 31, cb8 = tid >> 5;
        for (int cc = 0; cc < 8; cc++) {
            int c = cb8 * 8 + cc;
            s_z[pl * 65 + c] = zb[(size_t)c * 4096 + hw0 + pl];
        }
    }
    __syncthreads();
    if (tid < 32) {
        float s = 0.f;
        for (int c = 0; c < 64; c++) { float t = s_z[tid * 65 + c]; s += t * t; }
        s_z2[tid] = s;
    }
    const int j = tid & 7, p = tid >> 3;
    float best_d = FLT_MAX; int best_k = 0;
    for (int chunk = 0; chunk < 8; chunk++) {
        __syncthreads();
        for (int i = tid; i < 4096; i += 256) {
            int code = i >> 6, c = i & 63;
            s_cb[code * 65 + c] = cb[chunk * 4096 + i];
        }
        __syncthreads();
        float dot[8];
#pragma unroll
        for (int jj = 0; jj < 8; jj++) dot[jj] = 0.f;
        for (int c = 0; c < 64; c++) {
            float zc = s_z[p * 65 + c];
#pragma unroll
            for (int jj = 0; jj < 8; jj++) dot[jj] += zc * s_cb[(j + 8 * jj) * 65 + c];
        }
#pragma unroll
        for (int jj = 0; jj < 8; jj++) {
            int k = chunk * 64 + j + 8 * jj;
            float d = g_e2[k] - 2.f * dot[jj];
            if (d < best_d || (d == best_d && k < best_k)) { best_d = d; best_k = k; }
        }
    }
#pragma unroll
    for (int off = 4; off; off >>= 1) {
        float od = __shfl_down_sync(0xffffffffu, best_d, off);
        int   ok = __shfl_down_sync(0xffffffffu, best_k, off);
        if (od < best_d || (od == best_d && ok < best_k)) { best_d = od; best_k = ok; }
    }
    if (j == 0) { s_bd[p] = best_d; s_bk[p] = best_k; }
    __syncthreads();
    if (tid < 32) g_dmin[pos0 + tid] = s_z2[tid] + s_bd[tid];
    {
        int pl = tid & 31, cb8 = tid >> 5;
        float* zqb = g_zq + (size_t)b * 262144;
        int kidx = s_bk[pl];
        for (int cc = 0; cc < 8; cc++) {
            int c = cb8 * 8 + cc;
            zqb[(size_t)c * 4096 + hw0 + pl] = cb[kidx * 64 + c];
        }
    }
}

__global__ void k_loss(float* __restrict__ out_loss)
{
    __shared__ float sm[1024];
    int tid = threadIdx.x;
    float s = 0.f;
    for (int i = tid; i < 32768; i += 1024) s += g_dmin[i];
    sm[tid] = s;
    __syncthreads();
    for (int off = 512; off; off >>= 1) {
        if (tid < off) sm[tid] += sm[tid + off];
        __syncthreads();
    }
    if (tid == 0) out_loss[0] = sm[0] * (1.25f / 2097152.f);
}

// ---------------- launch ----------------
extern "C" void kernel_launch(void* const* d_in, const int* in_sizes, int n_in,
                              void* d_out, int out_size)
{
    const float* x   = (const float*)d_in[0];
    const float* ew1 = (const float*)d_in[1];
    const float* eb1 = (const float*)d_in[2];
    const float* ew2 = (const float*)d_in[3];
    const float* eb2 = (const float*)d_in[4];
    const float* ew3 = (const float*)d_in[5];
    const float* eb3 = (const float*)d_in[6];
    const float* ew4 = (const float*)d_in[7];
    const float* eb4 = (const float*)d_in[8];
    const float* cb  = (const float*)d_in[9];
    const float* dw1 = (const float*)d_in[10];
    const float* db1 = (const float*)d_in[11];
    const float* tw1 = (const float*)d_in[12];
    const float* tb1 = (const float*)d_in[13];
    const float* tw2 = (const float*)d_in[14];
    const float* tb2 = (const float*)d_in[15];
    const float* tw3 = (const float*)d_in[16];
    const float* tb3 = (const float*)d_in[17];
    float* out = (float*)d_out;

    // weight prep
    k_prep_oihw<<<64 * 16, 64>>>(ew2, 16, 1);
    k_prep_oihw<<<64 * 16, 64>>>(ew3, 16, 2);
    k_prep_oihw<<<64 * 9, 64>>>(ew4, 9, 3);
    k_prep_oihw<<<64 * 9, 64>>>(dw1, 9, 4);
    k_prep_t<<<1024, 64>>>(tw1, 5);
    k_prep_t<<<1024, 64>>>(tw2, 6);
    k_e2<<<1, 512>>>(cb);

    // encoder
    k_conv1<<<2048, 256>>>(x, ew1, eb1);                            // x  -> a1
    k_gconv4<<<dim3(128, 8), 128>>>(1, 1, eb2, 2, 256, 256);        // a1 -> a2
    k_gconv4<<<dim3(32, 8), 128>>>(2, 2, eb3, 3, 128, 128);         // a2 -> a3
    k_gconv3<<<dim3(32, 8), 128>>>(3, 3, eb4, 4, 0);                // a3 -> z

    // VQ
    k_vq<<<1024, 256>>>(cb);
    k_loss<<<1, 1024>>>(out + (out_size - 1));

    // decoder
    k_gconv3<<<dim3(32, 8), 128>>>(5, 4, db1, 6, 1);                // zq -> d1
    k_gconvt<<<dim3(32, 8, 4), 128>>>(6, 5, tb1, 2, 64, 64);        // d1 -> a2
    k_gconvt<<<dim3(128, 8, 4), 128>>>(2, 6, tb2, 1, 128, 128);     // a2 -> a1
    k_convt_out<<<dim3(16, 16, 8), 256>>>(tw3, tb3, out);           // a1 -> out
}